// round 10
// baseline (speedup 1.0000x reference)
#include <cuda_runtime.h>
#include <cstdint>
#include <cstddef>

#define Bn 128
#define Tn 2048
#define Cn 128
#define TSTRIDE 132  // padded row stride for transposed transitions in smem (backward)

// Scratch: all forward alphas (exact fp32). __device__ global (no runtime alloc).
__device__ __align__(16) float g_alpha[(size_t)Bn * Tn * Cn];

__device__ __forceinline__ unsigned long long pack2(float lo, float hi) {
    unsigned long long r;
    asm("mov.b64 %0, {%1, %2};" : "=l"(r) : "f"(lo), "f"(hi));
    return r;
}
__device__ __forceinline__ unsigned long long add2(unsigned long long a, unsigned long long b) {
    unsigned long long r;
    asm("add.rn.f32x2 %0, %1, %2;" : "=l"(r) : "l"(a), "l"(b));
    return r;
}
__device__ __forceinline__ float lo32(unsigned long long v) {
    return __uint_as_float((unsigned)v);
}
__device__ __forceinline__ float hi32(unsigned long long v) {
    return __uint_as_float((unsigned)(v >> 32));
}

// Exact monotone float->int key (no NaNs in this data).
__device__ __forceinline__ int fkey(float f) {
    int b = __float_as_int(f);
    return b ^ ((b >> 31) & 0x7fffffff);
}

// Warp-collective argmax over 128 values (lane l holds indices 4l..4l+3)
// using ONLY shfl/vote. Returns SMALLEST index achieving the max.
__device__ __forceinline__ int warp_argmax4_shfl(float4 v, int l) {
    int k0 = fkey(v.x), k1 = fkey(v.y), k2 = fkey(v.z), k3 = fkey(v.w);
    int km = max(max(k0, k1), max(k2, k3));

    int wm = km;
    wm = max(wm, __shfl_xor_sync(0xffffffffu, wm, 16));
    wm = max(wm, __shfl_xor_sync(0xffffffffu, wm, 8));
    wm = max(wm, __shfl_xor_sync(0xffffffffu, wm, 4));
    wm = max(wm, __shfl_xor_sync(0xffffffffu, wm, 2));
    wm = max(wm, __shfl_xor_sync(0xffffffffu, wm, 1));

    // Lane-local first slot equal to km (independent of wm: off critical path).
    int loc = (k0 == km) ? 0 : ((k1 == km) ? 1 : ((k2 == km) ? 2 : 3));

    unsigned ball = __ballot_sync(0xffffffffu, km == wm);
    int lane = __ffs(ball) - 1;
    int locw = __shfl_sync(0xffffffffu, loc, lane);
    return 4 * lane + locw;
}

// ============================ FORWARD ============================
// 2 batches per CTA, 1024 threads. Thread = (b2, j, c): c in {0..3} quad-splits i
// (32 i's each: SAME chain depth as the R8 single-batch kernel), j = class,
// b2 = batch-within-CTA. One __syncthreads serves both batches.
__global__ __launch_bounds__(1024, 1)
void viterbi_fwd(const float* __restrict__ pot,
                 const float* __restrict__ trans) {
    __shared__ __align__(16) float sb[2][2][Cn];  // [parity][b2][j]

    const int tid = threadIdx.x;
    const int c = tid & 3;            // i-chunk within quad
    const int j = (tid >> 2) & 127;   // class handled by this thread-quad
    const int b2 = tid >> 9;          // batch-within-CTA (0/1)
    const int b = blockIdx.x * 2 + b2;

    // Per-thread transition regs: i = 16g + 4c + {0..3}, column j, packed.
    unsigned long long tr2[16];
    #pragma unroll
    for (int g = 0; g < 8; ++g) {
        int i0 = 16 * g + 4 * c;
        float t0 = trans[(i0 + 0) * Cn + j];
        float t1 = trans[(i0 + 1) * Cn + j];
        float t2 = trans[(i0 + 2) * Cn + j];
        float t3 = trans[(i0 + 3) * Cn + j];
        tr2[2 * g]     = pack2(t0, t1);
        tr2[2 * g + 1] = pack2(t2, t3);
    }

    const float* potp = pot + (size_t)b * Tn * Cn + j;
    float* aout = g_alpha + (size_t)b * Tn * Cn + j;

    // t = 0
    if (c == 0) {
        float a0 = potp[0];
        sb[0][b2][j] = a0;
        aout[0] = a0;
    }

    // Potentials prefetch ring (distance 4); only c<2 lanes participate
    // (lane-level predicate -> @P LDG, no branch region).
    const bool pfl = (c < 2);
    float pr[4] = {0.f, 0.f, 0.f, 0.f};
    if (pfl) {
        pr[1] = potp[(size_t)1 * Cn];
        pr[2] = potp[(size_t)2 * Cn];
        pr[3] = potp[(size_t)3 * Cn];
        pr[0] = potp[(size_t)4 * Cn];
    }

    __syncthreads();

    int p = 0;

    // One branch-free step. PF: compile-time prefetch switch.
    auto step = [&](int t, bool PF) {
        float potv = pr[t & 3];
        if (PF && pfl) {
            int idx = min(t + 4, Tn - 1);                 // clamp: no guard branch
            pr[t & 3] = potp[(size_t)idx * Cn];
        }

        const ulonglong2* ab = (const ulonglong2*)sb[p][b2];
        float g0[8];
        #pragma unroll
        for (int g = 0; g < 8; ++g) {
            ulonglong2 a = ab[4 * g + c];  // 16B: alpha[16g+4c .. +3]
            unsigned long long s01 = add2(a.x, tr2[2 * g]);
            unsigned long long s23 = add2(a.y, tr2[2 * g + 1]);
            g0[g] = fmaxf(fmaxf(lo32(s01), hi32(s01)), fmaxf(lo32(s23), hi32(s23)));
        }
        float h0 = fmaxf(g0[0], g0[1]);
        float h1 = fmaxf(g0[2], g0[3]);
        float h2 = fmaxf(g0[4], g0[5]);
        float h3 = fmaxf(g0[6], g0[7]);
        float best = fmaxf(fmaxf(h0, h1), fmaxf(h2, h3));
        // butterfly: c-lanes 0/1 end with the full max
        best = fmaxf(best, __shfl_xor_sync(0xffffffffu, best, 1));
        best = fmaxf(best, __shfl_xor_sync(0xffffffffu, best, 2));

        float alpha = best + potv;
        if (c == 0) sb[p ^ 1][b2][j] = alpha;       // @P STS
        if (c == 1) aout[(size_t)t * Cn] = alpha;   // @P STG (off the STS lane)
        __syncthreads();
        p ^= 1;
    };

    // Main: t = 1 .. 2044 (511 branch-free blocks of 4), tail 3 steps.
    for (int tb = 1; tb <= Tn - 7; tb += 4) {
        step(tb + 0, true);
        step(tb + 1, true);
        step(tb + 2, true);
        step(tb + 3, true);
    }
    step(Tn - 3, false);
    step(Tn - 2, false);
    step(Tn - 1, false);
}

// ============================ BACKWARD ============================
__global__ __launch_bounds__(128, 1)
void viterbi_bwd(const float* __restrict__ trans,
                 float* __restrict__ out) {
    extern __shared__ float tT[];  // [Cn][TSTRIDE]: tT[j*TSTRIDE + i] = trans[i][j]

    const int b = blockIdx.x;
    const int tid = threadIdx.x;

    // Build transposed transitions in smem (coalesced reads across tid).
    {
        int j0 = tid;  // 0..127
        #pragma unroll 8
        for (int i = 0; i < Cn; ++i) {
            tT[j0 * TSTRIDE + i] = trans[i * Cn + j0];
        }
    }
    __syncthreads();

    if (tid < 32) {
        const int l = tid;
        float* ob = out + (size_t)b * Tn;
        const float4* arow = (const float4*)(g_alpha + (size_t)b * Tn * Cn);

        // last tag = argmax over alpha_{T-1}
        float4 av = arow[(size_t)(Tn - 1) * 32 + l];
        int tag = warp_argmax4_shfl(av, l);
        if (l == 0) ob[Tn - 1] = (float)tag;

        // Prefetch alpha rows 8 deep: pf[u] = row (2046 - u).
        float4 pf[8];
        #pragma unroll
        for (int u = 0; u < 8; ++u) {
            pf[u] = arow[(size_t)(Tn - 2 - u) * 32 + l];
        }

        // One trace step; PF=true: unconditional prefetch of row t-8 (in range);
        // PF=false: clamped prefetch, still branch-free.
        auto tstep = [&](int t, int u, bool PF) {
            float4 a = pf[u];
            if (PF) {
                pf[u] = arow[(size_t)(t - 8) * 32 + l];
            } else {
                int idx = max(t - 8, 0);                 // clamp: no guard branch
                pf[u] = arow[(size_t)idx * 32 + l];
            }
            const float4* trow = (const float4*)(tT + tag * TSTRIDE);
            float4 tv = trow[l];
            float4 s;
            s.x = a.x + tv.x;
            s.y = a.y + tv.y;
            s.z = a.z + tv.z;
            s.w = a.w + tv.w;
            tag = warp_argmax4_shfl(s, l);
            if (l == 0) ob[t] = (float)tag;              // @P STG
        };

        // Main: t = 2046 .. 15 (254 blocks of 8, fully branch-free).
        for (int tb = Tn - 2; tb >= 22; tb -= 8) {
            #pragma unroll
            for (int u = 0; u < 8; ++u) {
                tstep(tb - u, u, true);
            }
        }
        // Tail A: t = 14 .. 7 (clamped prefetch fills rows 6..0 into pf[0..6]).
        #pragma unroll
        for (int u = 0; u < 8; ++u) {
            tstep(14 - u, u, false);
        }
        // Tail B: t = 6 .. 0 (no prefetch needed; pf[0..6] hold rows 6..0).
        #pragma unroll
        for (int u = 0; u < 7; ++u) {
            int t = 6 - u;
            float4 a = pf[u];
            const float4* trow = (const float4*)(tT + tag * TSTRIDE);
            float4 tv = trow[l];
            float4 s;
            s.x = a.x + tv.x;
            s.y = a.y + tv.y;
            s.z = a.z + tv.z;
            s.w = a.w + tv.w;
            tag = warp_argmax4_shfl(s, l);
            if (l == 0) ob[t] = (float)tag;
        }
    }
}

extern "C" void kernel_launch(void* const* d_in, const int* in_sizes, int n_in,
                              void* d_out, int out_size) {
    const float* inputs = (const float*)d_in[0];       // [B, T, C] f32
    const float* transitions = (const float*)d_in[1];  // [C, C] f32
    float* out = (float*)d_out;                        // [B, T] f32 (tags)

    viterbi_fwd<<<Bn / 2, 1024>>>(inputs, transitions);

    const int bwd_smem = Cn * TSTRIDE * (int)sizeof(float);  // ~67.6KB
    cudaFuncSetAttribute(viterbi_bwd, cudaFuncAttributeMaxDynamicSharedMemorySize, bwd_smem);
    viterbi_bwd<<<Bn, 128, bwd_smem>>>(transitions, out);
}